// round 11
// baseline (speedup 1.0000x reference)
#include <cuda_runtime.h>
#include <math.h>

#define BB 4
#define MM 2048
#define CC 256
#define HH 4
#define HD 64
#define LL 9
#define TOK1 (BB*MM)          // 8192
#define TOT  (2*TOK1)         // 16384
#define SEQ2 ((long)MM*MM)

// scratch (static device arrays; no allocations allowed)
__device__ float g_X[TOT*CC];
__device__ float g_cosb[TOT*HD];
__device__ float g_sinb[TOT*HD];
__device__ float g_qkv[TOT*3*CC];
__device__ float g_attn[TOT*CC];
__device__ float g_msg[TOT*CC];
__device__ float g_h[TOT*2*CC];
__device__ float g_qk[TOT*CC];
__device__ float g_v[TOT*CC];
__device__ float g_S[32*SEQ2];
__device__ float g_P[32*SEQ2];
__device__ float g_cmax[16*MM];
__device__ float g_csum[16*MM];
__device__ float g_rK[BB*MM];
__device__ float g_cK[BB*MM];
__device__ float g_z[TOT];
__device__ float g_max0[BB*MM];
__device__ int   g_am0[BB*MM];
__device__ int   g_am1[BB*MM];
__device__ int   g_vld0[BB*MM];

// ---------------- common tensor-core helpers ----------------
__device__ __forceinline__ void mma8(float* c, const unsigned* a, const unsigned* b){
    asm volatile(
      "mma.sync.aligned.m16n8k8.row.col.f32.tf32.tf32.f32 "
      "{%0,%1,%2,%3},{%4,%5,%6,%7},{%8,%9},{%0,%1,%2,%3};"
      : "+f"(c[0]),"+f"(c[1]),"+f"(c[2]),"+f"(c[3])
      : "r"(a[0]),"r"(a[1]),"r"(a[2]),"r"(a[3]),"r"(b[0]),"r"(b[1]));
}
// hi = top-19-bit truncation (what HMMA.TF32 consumes); lo = exact residual.
__device__ __forceinline__ void hspl(float v, unsigned& hi, unsigned& lo){
    unsigned u=__float_as_uint(v)&0xFFFFE000u;
    hi=u;
    lo=__float_as_uint(__fsub_rn(v,__uint_as_float(u)));
}
__device__ __forceinline__ unsigned sptr(const void* p){
    return (unsigned)__cvta_generic_to_shared(p);
}
__device__ __forceinline__ void cpa16(unsigned dst, const void* src){
    asm volatile("cp.async.cg.shared.global [%0],[%1],16;"::"r"(dst),"l"(src));
}
__device__ __forceinline__ void cpc(){ asm volatile("cp.async.commit_group;"); }
__device__ __forceinline__ void cpw0(){ asm volatile("cp.async.wait_group 0;"); }
__device__ __forceinline__ void cpw1(){ asm volatile("cp.async.wait_group 1;"); }

// ---------------- 3xTF32 GEMM, cp.async 3-stage pipelined ----------------
// C[M,N] = os*(A@B(^T) + bias) + resid ; batched with (batch,head) strides.
template<int BN,int WM,int WN,bool TB>
__global__ void __launch_bounds__(256,2)
tgemm_k(const float* __restrict__ A, const float* __restrict__ Bm,
        const float* __restrict__ bias, const float* __restrict__ resid,
        float* __restrict__ C, int Kd, int lda,int ldb,int ldc,
        long sAb,long sAh,long sBb,long sBh,long sCb,long sCh,int Hs,float os)
{
    constexpr int BM=128;
    constexpr int MT=WM/16, NT2=WN/8;
    constexpr int NWC=BN/WN;
    constexpr int NB=BN/64;
    constexpr int BR  = TB ? BN : 16;
    constexpr int BCL = TB ? 20 : BN+8;
    __shared__ __align__(16) float As[3][BM][20];
    __shared__ __align__(16) float Bs[3][BR][BCL];

    const int z=blockIdx.z, zb=z/Hs, zh=z-zb*Hs;
    A +=(long)zb*sAb+(long)zh*sAh;
    Bm+=(long)zb*sBb+(long)zh*sBh;
    C +=(long)zb*sCb+(long)zh*sCh;
    const float* Rp = resid? resid+(long)zb*sCb+(long)zh*sCh : (const float*)0;

    const int tid=threadIdx.x;
    const int warp=tid>>5, lane=tid&31, gid=lane>>2, tig=lane&3;
    const int wR=warp/NWC, wC=warp%NWC;
    const int bm0=blockIdx.y*BM, bn0=blockIdx.x*BN;
    const int arow=tid>>2, akc=tid&3;

    float cr[MT][NT2][4];
    #pragma unroll
    for(int i=0;i<MT;i++)
        #pragma unroll
        for(int j=0;j<NT2;j++)
            #pragma unroll
            for(int q=0;q<4;q++) cr[i][j][q]=0.f;

    auto loadA=[&](int st,int k0){
        #pragma unroll
        for(int i=0;i<2;i++){
            int row=arow+i*64;
            cpa16(sptr(&As[st][row][akc*4]), A+(long)(bm0+row)*lda+k0+akc*4);
        }
    };
    auto loadB=[&](int st,int k0){
        if(!TB){
            #pragma unroll
            for(int i=0;i<NB;i++){
                int k = (BN==128)? (tid>>5)+i*8 : (tid>>4);
                int nc= (BN==128)? (tid&31)    : (tid&15);
                cpa16(sptr(&Bs[st][k][nc*4]), Bm+(long)(k0+k)*ldb+bn0+nc*4);
            }
        } else {
            #pragma unroll
            for(int i=0;i<NB;i++){
                int n=arow+i*64;
                cpa16(sptr(&Bs[st][n][akc*4]), Bm+(long)(bn0+n)*ldb+k0+akc*4);
            }
        }
    };

    const int nk=Kd/16;   // nk >= 4 for all shapes used
    loadA(0,0); loadB(0,0); cpc();
    loadA(1,16); loadB(1,16); cpc();

    for(int it=0; it<nk; it++){
        if(it+1<nk) cpw1(); else cpw0();   // stage `it` is resident
        __syncthreads();
        if(it+2<nk){
            int s=(it+2)%3;
            loadA(s,(it+2)*16); loadB(s,(it+2)*16); cpc();
        }
        const int st=it%3;

        #pragma unroll
        for(int ks=0;ks<2;ks++){
            const int k=ks*8+tig;
            unsigned ah[MT][4], al[MT][4];
            #pragma unroll
            for(int mi=0;mi<MT;mi++){
                int r=wR*WM+mi*16+gid;
                hspl(As[st][r][k],     ah[mi][0], al[mi][0]);
                hspl(As[st][r+8][k],   ah[mi][1], al[mi][1]);
                hspl(As[st][r][k+4],   ah[mi][2], al[mi][2]);
                hspl(As[st][r+8][k+4], ah[mi][3], al[mi][3]);
            }
            unsigned bh[NT2][2], bl[NT2][2];
            #pragma unroll
            for(int ni=0;ni<NT2;ni++){
                int cn=wC*WN+ni*8+gid;
                if(TB){
                    hspl(Bs[st][cn][k],   bh[ni][0], bl[ni][0]);
                    hspl(Bs[st][cn][k+4], bh[ni][1], bl[ni][1]);
                } else {
                    hspl(Bs[st][k][cn],   bh[ni][0], bl[ni][0]);
                    hspl(Bs[st][k+4][cn], bh[ni][1], bl[ni][1]);
                }
            }
            #pragma unroll
            for(int mi=0;mi<MT;mi++)
                #pragma unroll
                for(int ni=0;ni<NT2;ni++){
                    mma8(cr[mi][ni],ah[mi],bl[ni]);
                    mma8(cr[mi][ni],al[mi],bh[ni]);
                    mma8(cr[mi][ni],ah[mi],bh[ni]);
                }
        }
    }

    #pragma unroll
    for(int mi=0;mi<MT;mi++){
        #pragma unroll
        for(int ni=0;ni<NT2;ni++){
            long r0=bm0+wR*WM+mi*16+gid;
            int  cn=bn0+wC*WN+ni*8+2*tig;
            float b0=bias?bias[cn]:0.f, b1=bias?bias[cn+1]:0.f;
            float v0=(cr[mi][ni][0]+b0)*os, v1=(cr[mi][ni][1]+b1)*os;
            float v2=(cr[mi][ni][2]+b0)*os, v3=(cr[mi][ni][3]+b1)*os;
            if(Rp){
                v0+=Rp[r0*ldc+cn];     v1+=Rp[r0*ldc+cn+1];
                v2+=Rp[(r0+8)*ldc+cn]; v3+=Rp[(r0+8)*ldc+cn+1];
            }
            *reinterpret_cast<float2*>(&C[r0*ldc+cn])    =make_float2(v0,v1);
            *reinterpret_cast<float2*>(&C[(r0+8)*ldc+cn])=make_float2(v2,v3);
        }
    }
}

// ---------------- elementwise / reduction kernels ----------------
__global__ void posenc_k(const float* __restrict__ k0,const float* __restrict__ k1,
                         const float* __restrict__ Wr,const float* __restrict__ isz,
                         float* __restrict__ cb,float* __restrict__ sb)
{
    int idx=blockIdx.x*256+threadIdx.x;
    if(idx>=TOT*32) return;
    int t=idx>>5, p=idx&31;
    const float* kp=(t<TOK1)? k0+(long)t*2 : k1+(long)(t-TOK1)*2;
    float w=isz[0],h=isz[1],sc=0.5f*fmaxf(w,h);
    float nx=(kp[0]-0.5f*w)/sc, ny=(kp[1]-0.5f*h)/sc;
    float pr=nx*Wr[p]+ny*Wr[32+p];
    float c=cosf(pr), s=sinf(pr);
    cb[t*HD+2*p]=c; cb[t*HD+2*p+1]=c;
    sb[t*HD+2*p]=s; sb[t*HD+2*p+1]=s;
}

__global__ void rope_k(float* __restrict__ qkv,const float* __restrict__ cb,const float* __restrict__ sb)
{
    int idx=blockIdx.x*256+threadIdx.x;
    if(idx>=TOT*256) return;
    int t=idx>>8, p=idx&255, c0=p*2, d=c0&63;
    float c=cb[t*HD+d], s=sb[t*HD+d];
    float* q=qkv+(long)t*768+c0;
    float a=q[0], b=q[1];
    q[0]=a*c-b*s; q[1]=b*c+a*s;
}

__global__ void rsm_k(const float* __restrict__ S,float* __restrict__ P)
{
    long row=blockIdx.x;
    const float* x=S+row*(long)MM; float* y=P+row*(long)MM;
    int tid=threadIdx.x;
    float v[8], m=-1e30f;
    #pragma unroll
    for(int r=0;r<8;r++){ v[r]=x[tid+r*256]; m=fmaxf(m,v[r]); }
    __shared__ float red[256];
    red[tid]=m; __syncthreads();
    for(int s=128;s>0;s>>=1){ if(tid<s) red[tid]=fmaxf(red[tid],red[tid+s]); __syncthreads(); }
    m=red[0]; __syncthreads();
    float sum=0.f;
    #pragma unroll
    for(int r=0;r<8;r++){ v[r]=__expf(v[r]-m); sum+=v[r]; }
    red[tid]=sum; __syncthreads();
    for(int s=128;s>0;s>>=1){ if(tid<s) red[tid]+=red[tid+s]; __syncthreads(); }
    float inv=1.f/red[0];
    #pragma unroll
    for(int r=0;r<8;r++) y[tid+r*256]=v[r]*inv;
}

__global__ void cstat_k(const float* __restrict__ S,float* __restrict__ cm,float* __restrict__ cs)
{
    int j=blockIdx.x*blockDim.x+threadIdx.x, z=blockIdx.y;
    const float* b=S+(long)z*SEQ2+j;
    float m=-1e30f,s=0.f;
    for(int i=0;i<MM;i++){
        float v=b[(long)i*MM];
        if(v>m){ s=s*__expf(m-v)+1.f; m=v; } else s+=__expf(v-m);
    }
    cm[z*MM+j]=m; cs[z*MM+j]=s;
}

__global__ void tsm_k(const float* __restrict__ S,const float* __restrict__ cm,
                      const float* __restrict__ cs,float* __restrict__ PT)
{
    __shared__ float tile[32][33];
    int z=blockIdx.z; long base=(long)z*SEQ2;
    int m0=blockIdx.y*32, c0=blockIdx.x*32, tx=threadIdx.x, ty=threadIdx.y;
    #pragma unroll
    for(int r=0;r<4;r++){ int mm=ty+r*8; tile[mm][tx]=S[base+(long)(m0+mm)*MM+c0+tx]; }
    __syncthreads();
    #pragma unroll
    for(int r=0;r<4;r++){
        int nn=ty+r*8;
        float mx=cm[z*MM+c0+nn], inv=1.f/cs[z*MM+c0+nn];
        PT[base+(long)(c0+nn)*MM+m0+tx]=__expf(tile[tx][nn]-mx)*inv;
    }
}

__device__ __forceinline__ float gelu_t(float y){
    return 0.5f*y*(1.f+tanhf(0.7978845608028654f*(y+0.044715f*y*y*y)));
}

__global__ void lng_k(float* __restrict__ h,const float* __restrict__ g,const float* __restrict__ bt)
{
    long row=blockIdx.x; float* x=h+row*512;
    int tid=threadIdx.x;
    float a=x[tid], b=x[tid+256];
    __shared__ float s1[256],s2[256];
    s1[tid]=a+b; s2[tid]=a*a+b*b; __syncthreads();
    for(int s=128;s>0;s>>=1){ if(tid<s){ s1[tid]+=s1[tid+s]; s2[tid]+=s2[tid+s]; } __syncthreads(); }
    float mu=s1[0]*(1.f/512.f), var=s2[0]*(1.f/512.f)-mu*mu, rs=rsqrtf(var+1e-5f);
    x[tid]    =gelu_t((a-mu)*rs*g[tid]    +bt[tid]);
    x[tid+256]=gelu_t((b-mu)*rs*g[tid+256]+bt[tid+256]);
}

__global__ void gemv_k(const float* __restrict__ X,const float* __restrict__ w,
                       const float* __restrict__ b,float* __restrict__ z,int rows)
{
    int gw=(blockIdx.x*blockDim.x+threadIdx.x)>>5, lane=threadIdx.x&31;
    if(gw>=rows) return;
    const float* xr=X+(long)gw*CC;
    float s=0.f;
    for(int c=lane;c<CC;c+=32) s+=xr[c]*w[c];
    for(int o=16;o;o>>=1) s+=__shfl_down_sync(0xffffffffu,s,o);
    if(!lane) z[gw]=s+b[0];
}

__global__ void rlse_k(const float* __restrict__ sim,float* __restrict__ rK)
{
    long row=blockIdx.x;
    const float* x=sim+row*(long)MM;
    int tid=threadIdx.x;
    float v[8], m=-1e30f;
    #pragma unroll
    for(int r=0;r<8;r++){ v[r]=x[tid+r*256]; m=fmaxf(m,v[r]); }
    __shared__ float red[256];
    red[tid]=m; __syncthreads();
    for(int s=128;s>0;s>>=1){ if(tid<s) red[tid]=fmaxf(red[tid],red[tid+s]); __syncthreads(); }
    m=red[0]; __syncthreads();
    float sum=0.f;
    #pragma unroll
    for(int r=0;r<8;r++) sum+=__expf(v[r]-m);
    red[tid]=sum; __syncthreads();
    for(int s=128;s>0;s>>=1){ if(tid<s) red[tid]+=red[tid+s]; __syncthreads(); }
    if(!tid) rK[row]=m+logf(red[0]);
}

__global__ void clse_k(const float* __restrict__ sim,float* __restrict__ cK)
{
    int j=blockIdx.x*256+threadIdx.x, b=blockIdx.y;
    const float* base=sim+(long)b*SEQ2+j;
    float m=-1e30f,s=0.f;
    for(int i=0;i<MM;i++){
        float v=base[(long)i*MM];
        if(v>m){ s=s*__expf(m-v)+1.f; m=v; } else s+=__expf(v-m);
    }
    cK[b*MM+j]=m+logf(s);
}

__device__ __forceinline__ float logsigf(float x){
    return (x>=0.f)? -log1pf(__expf(-x)) : x-log1pf(__expf(x));
}

__global__ void fill_k(const float* __restrict__ sim,const float* __restrict__ rK,
                       const float* __restrict__ cK,const float* __restrict__ z0,
                       const float* __restrict__ z1,float* __restrict__ out)
{
    int j=blockIdx.x*256+threadIdx.x;
    if(j>MM) return;
    int bi=blockIdx.y, b=bi/(MM+1), i=bi-b*(MM+1);
    float v;
    if(i<MM&&j<MM)
        v=2.f*sim[(long)b*SEQ2+(long)i*MM+j]-rK[b*MM+i]-cK[b*MM+j]
          +logsigf(z0[b*MM+i])+logsigf(z1[b*MM+j]);
    else if(i<MM) v=logsigf(-z0[b*MM+i]);
    else if(j<MM) v=logsigf(-z1[b*MM+j]);
    else v=0.f;
    out[((long)b*(MM+1)+i)*(MM+1)+j]=v;
}

__global__ void ramx_k(const float* __restrict__ sc,float* __restrict__ mx,int* __restrict__ am)
{
    long row=blockIdx.x;
    int b=(int)(row>>11), i=(int)(row&2047);
    const float* x=sc+((long)b*(MM+1)+i)*(MM+1);
    int tid=threadIdx.x;
    float best=-1e30f; int bi=0;
    for(int j=tid;j<MM;j+=256){ float v=x[j]; if(v>best){best=v;bi=j;} }
    __shared__ float rv[256]; __shared__ int ri[256];
    rv[tid]=best; ri[tid]=bi; __syncthreads();
    for(int s=128;s>0;s>>=1){
        if(tid<s && (rv[tid+s]>rv[tid]||(rv[tid+s]==rv[tid]&&ri[tid+s]<ri[tid]))){
            rv[tid]=rv[tid+s]; ri[tid]=ri[tid+s];
        }
        __syncthreads();
    }
    if(!tid){ mx[row]=rv[0]; am[row]=ri[0]; }
}

__global__ void camx_k(const float* __restrict__ sc,int* __restrict__ am)
{
    int j=blockIdx.x*256+threadIdx.x, b=blockIdx.y;
    const float* base=sc+(long)b*(MM+1)*(MM+1)+j;
    float best=-1e30f; int bi=0;
    for(int i=0;i<MM;i++){ float v=base[(long)i*(MM+1)]; if(v>best){best=v;bi=i;} }
    am[b*MM+j]=bi;
}

__global__ void mt0_k(const float* __restrict__ mx,const int* __restrict__ a0,const int* __restrict__ a1,
                      float* __restrict__ m0,float* __restrict__ ms0,int* __restrict__ v0)
{
    int idx=blockIdx.x*256+threadIdx.x;
    if(idx>=BB*MM) return;
    int b=idx>>11, i=idx&2047, aa=a0[idx];
    bool mut=(a1[b*MM+aa]==i);
    float sc=mut? __expf(mx[idx]) : 0.f;
    bool vv=mut&&(sc>0.1f);
    m0[idx]=vv? (float)aa : -1.f;
    ms0[idx]=sc;
    v0[idx]=vv?1:0;
}

__global__ void mt1_k(const int* __restrict__ a0,const int* __restrict__ a1,const float* __restrict__ ms0,
                      const int* __restrict__ v0,float* __restrict__ m1,float* __restrict__ ms1)
{
    int idx=blockIdx.x*256+threadIdx.x;
    if(idx>=BB*MM) return;
    int b=idx>>11, j=idx&2047, aa=a1[idx];
    bool mut=(a0[b*MM+aa]==j);
    ms1[idx]=mut? ms0[b*MM+aa] : 0.f;
    bool vv=mut&&(v0[b*MM+aa]!=0);
    m1[idx]=vv? (float)aa : -1.f;
}

// ---------------- host-side GEMM wrappers ----------------
struct BD{ long sAb,sAh,sBb,sBh,sCb,sCh; int Hs,nz; };

static void gnn(const float*A,const float*B,const float*bi,const float*rs,float*C,
                int M,int N,int K,int la,int lb,int lc,const BD&d,float os=1.f){
    dim3 g(N/128,M/128,d.nz);
    tgemm_k<128,64,32,false><<<g,256>>>(A,B,bi,rs,C,K,la,lb,lc,d.sAb,d.sAh,d.sBb,d.sBh,d.sCb,d.sCh,d.Hs,os);
}
static void gnt(const float*A,const float*B,const float*bi,const float*rs,float*C,
                int M,int N,int K,int la,int lb,int lc,const BD&d,float os=1.f){
    dim3 g(N/128,M/128,d.nz);
    tgemm_k<128,64,32,true><<<g,256>>>(A,B,bi,rs,C,K,la,lb,lc,d.sAb,d.sAh,d.sBb,d.sBh,d.sCb,d.sCh,d.Hs,os);
}
static void gnn64(const float*A,const float*B,float*C,int la,int lb,int lc,const BD&d){
    dim3 g(1,MM/128,d.nz);
    tgemm_k<64,32,32,false><<<g,256>>>(A,B,(const float*)0,(const float*)0,C,MM,la,lb,lc,d.sAb,d.sAh,d.sBb,d.sBh,d.sCb,d.sCh,d.Hs,1.f);
}

extern "C" void kernel_launch(void* const* d_in, const int* in_sizes, int n_in,
                              void* d_out, int out_size)
{
    const float *kp0=(const float*)d_in[0], *ds0=(const float*)d_in[1];
    const float *kp1=(const float*)d_in[2], *ds1=(const float*)d_in[3];
    const float *isz=(const float*)d_in[4], *Wr=(const float*)d_in[5];
    const float *sqW=(const float*)d_in[6], *sqB=(const float*)d_in[7];
    const float *soW=(const float*)d_in[8], *soB=(const float*)d_in[9];
    const float *sf1=(const float*)d_in[10],*sb1=(const float*)d_in[11];
    const float *sg =(const float*)d_in[12],*sbe=(const float*)d_in[13];
    const float *sf2=(const float*)d_in[14],*sb2=(const float*)d_in[15];
    const float *cqW=(const float*)d_in[16],*cqB=(const float*)d_in[17];
    const float *cvW=(const float*)d_in[18],*cvB=(const float*)d_in[19];
    const float *coW=(const float*)d_in[20],*coB=(const float*)d_in[21];
    const float *cf1=(const float*)d_in[22],*cb1=(const float*)d_in[23];
    const float *cg =(const float*)d_in[24],*cbe=(const float*)d_in[25];
    const float *cf2=(const float*)d_in[26],*cb2=(const float*)d_in[27];
    const float *fpW=(const float*)d_in[28],*fpB=(const float*)d_in[29];
    const float *mw =(const float*)d_in[30],*mb =(const float*)d_in[31];
    float* out=(float*)d_out;

    void* p;
    #define SYM(v,s) cudaGetSymbolAddress(&p,s); float* v=(float*)p;
    SYM(X,g_X) SYM(cb,g_cosb) SYM(sb,g_sinb) SYM(qkv,g_qkv) SYM(attn,g_attn)
    SYM(msg,g_msg) SYM(hb,g_h) SYM(qk,g_qk) SYM(vv,g_v)
    SYM(Sb,g_S) SYM(Pb,g_P) SYM(cm,g_cmax) SYM(cs,g_csum)
    SYM(rK,g_rK) SYM(cK,g_cK) SYM(zb,g_z) SYM(mx0,g_max0)
    #undef SYM
    cudaGetSymbolAddress(&p,g_am0);  int* am0=(int*)p;
    cudaGetSymbolAddress(&p,g_am1);  int* am1=(int*)p;
    cudaGetSymbolAddress(&p,g_vld0); int* vl0=(int*)p;

    cudaMemcpyAsync(X, ds0, (size_t)TOK1*CC*4, cudaMemcpyDeviceToDevice);
    cudaMemcpyAsync(X+(long)TOK1*CC, ds1, (size_t)TOK1*CC*4, cudaMemcpyDeviceToDevice);
    posenc_k<<<TOT*32/256,256>>>(kp0,kp1,Wr,isz,cb,sb);

    const BD one   ={0,0,0,0,0,0,1,1};
    const BD selfS ={2048L*768,64, 2048L*768,64, 4*SEQ2,SEQ2, 4,32};
    const BD selfPV={4*SEQ2,SEQ2, 2048L*768,64, 2048L*256,64, 4,32};
    const BD crosS ={2048L*256,64, 2048L*256,64, 4*SEQ2,SEQ2, 4,16};
    const BD crosPV={4*SEQ2,SEQ2, 2048L*256,64, 2048L*256,64, 4,16};
    const BD epiS  ={2048L*256,0, 2048L*256,0, SEQ2,0, 1,4};

    for(int i=0;i<LL;i++){
        // --- self block (d0 & d1 together) ---
        gnn(X, sqW+(long)i*CC*3*CC, sqB+(long)i*3*CC, 0, qkv, TOT,768,256, 256,768,768, one);
        rope_k<<<TOT,256>>>(qkv,cb,sb);
        gnt(qkv, qkv+256, 0,0, Sb, MM,MM,64, 768,768,MM, selfS, 0.125f);
        rsm_k<<<32*MM,256>>>(Sb,Pb);
        gnn64(Pb, qkv+512, attn, MM,768,256, selfPV);
        gnn(attn, soW+(long)i*CC*CC, soB+(long)i*CC, 0, msg, TOT,256,256, 256,256,256, one);
        // FFN1 split: h = X@W1[:256] + msg@W1[256:] + b1  (no cat buffer)
        gnn(X,   sf1+(long)i*512*512,           sb1+(long)i*512, 0,  hb, TOT,512,256, 256,512,512, one);
        gnn(msg, sf1+(long)i*512*512+256L*512,  0,               hb, hb, TOT,512,256, 256,512,512, one);
        lng_k<<<TOT,256>>>(hb, sg+(long)i*512, sbe+(long)i*512);
        gnn(hb, sf2+(long)i*512*256, sb2+(long)i*256, X, X, TOT,256,512, 512,256,256, one);
        // --- cross block ---
        gnn(X, cqW+(long)i*CC*CC, cqB+(long)i*CC, 0, qk, TOT,256,256, 256,256,256, one);
        gnn(X, cvW+(long)i*CC*CC, cvB+(long)i*CC, 0, vv, TOT,256,256, 256,256,256, one);
        gnt(qk, qk+(long)TOK1*CC, 0,0, Sb, MM,MM,64, 256,256,MM, crosS, 0.125f);
        rsm_k<<<16*MM,256>>>(Sb,Pb);
        cstat_k<<<dim3(8,16),256>>>(Sb,cm,cs);
        tsm_k<<<dim3(64,64,16),dim3(32,8)>>>(Sb,cm,cs,Pb+16*SEQ2);
        gnn64(Pb, vv+(long)TOK1*CC, attn, MM,256,256, crosPV);
        gnn64(Pb+16*SEQ2, vv, attn+(long)TOK1*CC, MM,256,256, crosPV);
        gnn(attn, coW+(long)i*CC*CC, coB+(long)i*CC, 0, msg, TOT,256,256, 256,256,256, one);
        gnn(X,   cf1+(long)i*512*512,           cb1+(long)i*512, 0,  hb, TOT,512,256, 256,512,512, one);
        gnn(msg, cf1+(long)i*512*512+256L*512,  0,               hb, hb, TOT,512,256, 256,512,512, one);
        lng_k<<<TOT,256>>>(hb, cg+(long)i*512, cbe+(long)i*512);
        gnn(hb, cf2+(long)i*512*256, cb2+(long)i*256, X, X, TOT,256,512, 512,256,256, one);
    }

    // --- matching epilogue ---
    gnn(X, fpW, fpB, 0, qk, TOT,256,256, 256,256,256, one, 0.25f);
    gnt(qk, qk+(long)TOK1*CC, 0,0, Sb, MM,MM,256, 256,256,MM, epiS);
    gemv_k<<<TOT/8,256>>>(X,mw,mb,zb,TOT);
    rlse_k<<<BB*MM,256>>>(Sb,rK);
    clse_k<<<dim3(8,BB),256>>>(Sb,cK);
    float* scores=out+4L*BB*MM;
    fill_k<<<dim3((MM+256)/256,BB*(MM+1)),256>>>(Sb,rK,cK,zb,zb+TOK1,scores);
    ramx_k<<<BB*MM,256>>>(scores,mx0,am0);
    camx_k<<<dim3(8,BB),256>>>(scores,am1);
    mt0_k<<<BB*MM/256,256>>>(mx0,am0,am1,out,out+2L*BB*MM,vl0);
    mt1_k<<<BB*MM/256,256>>>(am0,am1,out+2L*BB*MM,vl0,out+(long)BB*MM,out+3L*BB*MM);
}

// round 12
// speedup vs baseline: 1.4947x; 1.4947x over previous
#include <cuda_runtime.h>
#include <math.h>

#define BB 4
#define MM 2048
#define CC 256
#define HH 4
#define HD 64
#define LL 9
#define TOK1 (BB*MM)          // 8192
#define TOT  (2*TOK1)         // 16384
#define SEQ2 ((long)MM*MM)

// scratch (static device arrays; no allocations allowed)
__device__ float g_X[TOT*CC];
__device__ float g_cosb[TOT*HD];
__device__ float g_sinb[TOT*HD];
__device__ float g_qkv[TOT*3*CC];
__device__ float g_attn[TOT*CC];
__device__ float g_msg[TOT*CC];
__device__ float g_h[TOT*2*CC];
__device__ float g_qk[TOT*CC];
__device__ float g_v[TOT*CC];
__device__ float g_S[32*SEQ2];
__device__ float g_P[32*SEQ2];
__device__ float g_cmax[16*MM];
__device__ float g_csum[16*MM];
__device__ float g_rK[BB*MM];
__device__ float g_cK[BB*MM];
__device__ float g_z[TOT];
__device__ float g_max0[BB*MM];
__device__ int   g_am0[BB*MM];
__device__ int   g_am1[BB*MM];
__device__ int   g_vld0[BB*MM];

// ---------------- common tensor-core helpers ----------------
__device__ __forceinline__ void mma8(float* c, const unsigned* a, const unsigned* b){
    asm volatile(
      "mma.sync.aligned.m16n8k8.row.col.f32.tf32.tf32.f32 "
      "{%0,%1,%2,%3},{%4,%5,%6,%7},{%8,%9},{%0,%1,%2,%3};"
      : "+f"(c[0]),"+f"(c[1]),"+f"(c[2]),"+f"(c[3])
      : "r"(a[0]),"r"(a[1]),"r"(a[2]),"r"(a[3]),"r"(b[0]),"r"(b[1]));
}
// hi = top-19-bit truncation (what HMMA.TF32 consumes); lo = exact residual.
__device__ __forceinline__ void hspl(float v, unsigned& hi, unsigned& lo){
    unsigned u=__float_as_uint(v)&0xFFFFE000u;
    hi=u;
    lo=__float_as_uint(__fsub_rn(v,__uint_as_float(u)));
}
__device__ __forceinline__ unsigned sptr(const void* p){
    return (unsigned)__cvta_generic_to_shared(p);
}
__device__ __forceinline__ void cpa16(unsigned dst, const void* src){
    asm volatile("cp.async.cg.shared.global [%0],[%1],16;"::"r"(dst),"l"(src));
}
__device__ __forceinline__ void cpc(){ asm volatile("cp.async.commit_group;"); }
__device__ __forceinline__ void cpw0(){ asm volatile("cp.async.wait_group 0;"); }

// ---------------- 3xTF32 GEMM, cp.async double-buffered (R7-proven) ----------
// C[M,N] = os*(A@B(^T) + bias) + resid ; batched with (batch,head) strides.
template<int BN,int WM,int WN,bool TB>
__global__ void __launch_bounds__(256)
tgemm_k(const float* __restrict__ A, const float* __restrict__ Bm,
        const float* __restrict__ bias, const float* __restrict__ resid,
        float* __restrict__ C, int Kd, int lda,int ldb,int ldc,
        long sAb,long sAh,long sBb,long sBh,long sCb,long sCh,int Hs,float os)
{
    constexpr int BM=128;
    constexpr int MT=WM/16, NT2=WN/8;
    constexpr int NWC=BN/WN;
    constexpr int NB=BN/64;
    constexpr int BR  = TB ? BN : 16;
    constexpr int BCL = TB ? 20 : BN+8;
    __shared__ __align__(16) float As[2][BM][20];
    __shared__ __align__(16) float Bs[2][BR][BCL];

    const int z=blockIdx.z, zb=z/Hs, zh=z-zb*Hs;
    A +=(long)zb*sAb+(long)zh*sAh;
    Bm+=(long)zb*sBb+(long)zh*sBh;
    C +=(long)zb*sCb+(long)zh*sCh;
    const float* Rp = resid? resid+(long)zb*sCb+(long)zh*sCh : (const float*)0;

    const int tid=threadIdx.x;
    const int warp=tid>>5, lane=tid&31, gid=lane>>2, tig=lane&3;
    const int wR=warp/NWC, wC=warp%NWC;
    const int bm0=blockIdx.y*BM, bn0=blockIdx.x*BN;
    const int arow=tid>>2, akc=tid&3;

    float cr[MT][NT2][4];
    #pragma unroll
    for(int i=0;i<MT;i++)
        #pragma unroll
        for(int j=0;j<NT2;j++)
            #pragma unroll
            for(int q=0;q<4;q++) cr[i][j][q]=0.f;

    auto loadA=[&](int st,int k0){
        #pragma unroll
        for(int i=0;i<2;i++){
            int row=arow+i*64;
            cpa16(sptr(&As[st][row][akc*4]), A+(long)(bm0+row)*lda+k0+akc*4);
        }
    };
    auto loadB=[&](int st,int k0){
        if(!TB){
            #pragma unroll
            for(int i=0;i<NB;i++){
                int k = (BN==128)? (tid>>5)+i*8 : (tid>>4);
                int nc= (BN==128)? (tid&31)    : (tid&15);
                cpa16(sptr(&Bs[st][k][nc*4]), Bm+(long)(k0+k)*ldb+bn0+nc*4);
            }
        } else {
            #pragma unroll
            for(int i=0;i<NB;i++){
                int n=arow+i*64;
                cpa16(sptr(&Bs[st][n][akc*4]), Bm+(long)(bn0+n)*ldb+k0+akc*4);
            }
        }
    };

    const int nk=Kd/16;
    loadA(0,0); loadB(0,0); cpc();

    for(int it=0; it<nk; it++){
        cpw0(); __syncthreads();
        if(it+1<nk){ loadA((it+1)&1,(it+1)*16); loadB((it+1)&1,(it+1)*16); cpc(); }
        const int st=it&1;

        #pragma unroll
        for(int ks=0;ks<2;ks++){
            const int k=ks*8+tig;
            unsigned ah[MT][4], al[MT][4];
            #pragma unroll
            for(int mi=0;mi<MT;mi++){
                int r=wR*WM+mi*16+gid;
                hspl(As[st][r][k],     ah[mi][0], al[mi][0]);
                hspl(As[st][r+8][k],   ah[mi][1], al[mi][1]);
                hspl(As[st][r][k+4],   ah[mi][2], al[mi][2]);
                hspl(As[st][r+8][k+4], ah[mi][3], al[mi][3]);
            }
            unsigned bh[NT2][2], bl[NT2][2];
            #pragma unroll
            for(int ni=0;ni<NT2;ni++){
                int cn=wC*WN+ni*8+gid;
                if(TB){
                    hspl(Bs[st][cn][k],   bh[ni][0], bl[ni][0]);
                    hspl(Bs[st][cn][k+4], bh[ni][1], bl[ni][1]);
                } else {
                    hspl(Bs[st][k][cn],   bh[ni][0], bl[ni][0]);
                    hspl(Bs[st][k+4][cn], bh[ni][1], bl[ni][1]);
                }
            }
            #pragma unroll
            for(int mi=0;mi<MT;mi++)
                #pragma unroll
                for(int ni=0;ni<NT2;ni++){
                    mma8(cr[mi][ni],ah[mi],bl[ni]);
                    mma8(cr[mi][ni],al[mi],bh[ni]);
                    mma8(cr[mi][ni],ah[mi],bh[ni]);
                }
        }
    }

    #pragma unroll
    for(int mi=0;mi<MT;mi++){
        #pragma unroll
        for(int ni=0;ni<NT2;ni++){
            long r0=bm0+wR*WM+mi*16+gid;
            int  cn=bn0+wC*WN+ni*8+2*tig;
            float b0=bias?bias[cn]:0.f, b1=bias?bias[cn+1]:0.f;
            float v0=(cr[mi][ni][0]+b0)*os, v1=(cr[mi][ni][1]+b1)*os;
            float v2=(cr[mi][ni][2]+b0)*os, v3=(cr[mi][ni][3]+b1)*os;
            if(Rp){
                v0+=Rp[r0*ldc+cn];     v1+=Rp[r0*ldc+cn+1];
                v2+=Rp[(r0+8)*ldc+cn]; v3+=Rp[(r0+8)*ldc+cn+1];
            }
            *reinterpret_cast<float2*>(&C[r0*ldc+cn])    =make_float2(v0,v1);
            *reinterpret_cast<float2*>(&C[(r0+8)*ldc+cn])=make_float2(v2,v3);
        }
    }
}

// ---------------- elementwise / reduction kernels ----------------
__global__ void posenc_k(const float* __restrict__ k0,const float* __restrict__ k1,
                         const float* __restrict__ Wr,const float* __restrict__ isz,
                         float* __restrict__ cb,float* __restrict__ sb)
{
    int idx=blockIdx.x*256+threadIdx.x;
    if(idx>=TOT*32) return;
    int t=idx>>5, p=idx&31;
    const float* kp=(t<TOK1)? k0+(long)t*2 : k1+(long)(t-TOK1)*2;
    float w=isz[0],h=isz[1],sc=0.5f*fmaxf(w,h);
    float nx=(kp[0]-0.5f*w)/sc, ny=(kp[1]-0.5f*h)/sc;
    float pr=nx*Wr[p]+ny*Wr[32+p];
    float c=cosf(pr), s=sinf(pr);
    cb[t*HD+2*p]=c; cb[t*HD+2*p+1]=c;
    sb[t*HD+2*p]=s; sb[t*HD+2*p+1]=s;
}

__global__ void rope_k(float* __restrict__ qkv,const float* __restrict__ cb,const float* __restrict__ sb)
{
    int idx=blockIdx.x*256+threadIdx.x;
    if(idx>=TOT*256) return;
    int t=idx>>8, p=idx&255, c0=p*2, d=c0&63;
    float c=cb[t*HD+d], s=sb[t*HD+d];
    float* q=qkv+(long)t*768+c0;
    float a=q[0], b=q[1];
    q[0]=a*c-b*s; q[1]=b*c+a*s;
}

__global__ void rsm_k(const float* __restrict__ S,float* __restrict__ P)
{
    long row=blockIdx.x;
    const float* x=S+row*(long)MM; float* y=P+row*(long)MM;
    int tid=threadIdx.x;
    float v[8], m=-1e30f;
    #pragma unroll
    for(int r=0;r<8;r++){ v[r]=x[tid+r*256]; m=fmaxf(m,v[r]); }
    __shared__ float red[256];
    red[tid]=m; __syncthreads();
    for(int s=128;s>0;s>>=1){ if(tid<s) red[tid]=fmaxf(red[tid],red[tid+s]); __syncthreads(); }
    m=red[0]; __syncthreads();
    float sum=0.f;
    #pragma unroll
    for(int r=0;r<8;r++){ v[r]=__expf(v[r]-m); sum+=v[r]; }
    red[tid]=sum; __syncthreads();
    for(int s=128;s>0;s>>=1){ if(tid<s) red[tid]+=red[tid+s]; __syncthreads(); }
    float inv=1.f/red[0];
    #pragma unroll
    for(int r=0;r<8;r++) y[tid+r*256]=v[r]*inv;
}

__global__ void cstat_k(const float* __restrict__ S,float* __restrict__ cm,float* __restrict__ cs)
{
    int j=blockIdx.x*blockDim.x+threadIdx.x, z=blockIdx.y;
    const float* b=S+(long)z*SEQ2+j;
    float m=-1e30f,s=0.f;
    for(int i=0;i<MM;i++){
        float v=b[(long)i*MM];
        if(v>m){ s=s*__expf(m-v)+1.f; m=v; } else s+=__expf(v-m);
    }
    cm[z*MM+j]=m; cs[z*MM+j]=s;
}

__global__ void tsm_k(const float* __restrict__ S,const float* __restrict__ cm,
                      const float* __restrict__ cs,float* __restrict__ PT)
{
    __shared__ float tile[32][33];
    int z=blockIdx.z; long base=(long)z*SEQ2;
    int m0=blockIdx.y*32, c0=blockIdx.x*32, tx=threadIdx.x, ty=threadIdx.y;
    #pragma unroll
    for(int r=0;r<4;r++){ int mm=ty+r*8; tile[mm][tx]=S[base+(long)(m0+mm)*MM+c0+tx]; }
    __syncthreads();
    #pragma unroll
    for(int r=0;r<4;r++){
        int nn=ty+r*8;
        float mx=cm[z*MM+c0+nn], inv=1.f/cs[z*MM+c0+nn];
        PT[base+(long)(c0+nn)*MM+m0+tx]=__expf(tile[tx][nn]-mx)*inv;
    }
}

__device__ __forceinline__ float gelu_t(float y){
    return 0.5f*y*(1.f+tanhf(0.7978845608028654f*(y+0.044715f*y*y*y)));
}

__global__ void lng_k(float* __restrict__ h,const float* __restrict__ g,const float* __restrict__ bt)
{
    long row=blockIdx.x; float* x=h+row*512;
    int tid=threadIdx.x;
    float a=x[tid], b=x[tid+256];
    __shared__ float s1[256],s2[256];
    s1[tid]=a+b; s2[tid]=a*a+b*b; __syncthreads();
    for(int s=128;s>0;s>>=1){ if(tid<s){ s1[tid]+=s1[tid+s]; s2[tid]+=s2[tid+s]; } __syncthreads(); }
    float mu=s1[0]*(1.f/512.f), var=s2[0]*(1.f/512.f)-mu*mu, rs=rsqrtf(var+1e-5f);
    x[tid]    =gelu_t((a-mu)*rs*g[tid]    +bt[tid]);
    x[tid+256]=gelu_t((b-mu)*rs*g[tid+256]+bt[tid+256]);
}

__global__ void gemv_k(const float* __restrict__ X,const float* __restrict__ w,
                       const float* __restrict__ b,float* __restrict__ z,int rows)
{
    int gw=(blockIdx.x*blockDim.x+threadIdx.x)>>5, lane=threadIdx.x&31;
    if(gw>=rows) return;
    const float* xr=X+(long)gw*CC;
    float s=0.f;
    for(int c=lane;c<CC;c+=32) s+=xr[c]*w[c];
    for(int o=16;o;o>>=1) s+=__shfl_down_sync(0xffffffffu,s,o);
    if(!lane) z[gw]=s+b[0];
}

__global__ void rlse_k(const float* __restrict__ sim,float* __restrict__ rK)
{
    long row=blockIdx.x;
    const float* x=sim+row*(long)MM;
    int tid=threadIdx.x;
    float v[8], m=-1e30f;
    #pragma unroll
    for(int r=0;r<8;r++){ v[r]=x[tid+r*256]; m=fmaxf(m,v[r]); }
    __shared__ float red[256];
    red[tid]=m; __syncthreads();
    for(int s=128;s>0;s>>=1){ if(tid<s) red[tid]=fmaxf(red[tid],red[tid+s]); __syncthreads(); }
    m=red[0]; __syncthreads();
    float sum=0.f;
    #pragma unroll
    for(int r=0;r<8;r++) sum+=__expf(v[r]-m);
    red[tid]=sum; __syncthreads();
    for(int s=128;s>0;s>>=1){ if(tid<s) red[tid]+=red[tid+s]; __syncthreads(); }
    if(!tid) rK[row]=m+logf(red[0]);
}

__global__ void clse_k(const float* __restrict__ sim,float* __restrict__ cK)
{
    int j=blockIdx.x*256+threadIdx.x, b=blockIdx.y;
    const float* base=sim+(long)b*SEQ2+j;
    float m=-1e30f,s=0.f;
    for(int i=0;i<MM;i++){
        float v=base[(long)i*MM];
        if(v>m){ s=s*__expf(m-v)+1.f; m=v; } else s+=__expf(v-m);
    }
    cK[b*MM+j]=m+logf(s);
}

__device__ __forceinline__ float logsigf(float x){
    return (x>=0.f)? -log1pf(__expf(-x)) : x-log1pf(__expf(x));
}

__global__ void fill_k(const float* __restrict__ sim,const float* __restrict__ rK,
                       const float* __restrict__ cK,const float* __restrict__ z0,
                       const float* __restrict__ z1,float* __restrict__ out)
{
    int j=blockIdx.x*256+threadIdx.x;
    if(j>MM) return;
    int bi=blockIdx.y, b=bi/(MM+1), i=bi-b*(MM+1);
    float v;
    if(i<MM&&j<MM)
        v=2.f*sim[(long)b*SEQ2+(long)i*MM+j]-rK[b*MM+i]-cK[b*MM+j]
          +logsigf(z0[b*MM+i])+logsigf(z1[b*MM+j]);
    else if(i<MM) v=logsigf(-z0[b*MM+i]);
    else if(j<MM) v=logsigf(-z1[b*MM+j]);
    else v=0.f;
    out[((long)b*(MM+1)+i)*(MM+1)+j]=v;
}

__global__ void ramx_k(const float* __restrict__ sc,float* __restrict__ mx,int* __restrict__ am)
{
    long row=blockIdx.x;
    int b=(int)(row>>11), i=(int)(row&2047);
    const float* x=sc+((long)b*(MM+1)+i)*(MM+1);
    int tid=threadIdx.x;
    float best=-1e30f; int bi=0;
    for(int j=tid;j<MM;j+=256){ float v=x[j]; if(v>best){best=v;bi=j;} }
    __shared__ float rv[256]; __shared__ int ri[256];
    rv[tid]=best; ri[tid]=bi; __syncthreads();
    for(int s=128;s>0;s>>=1){
        if(tid<s && (rv[tid+s]>rv[tid]||(rv[tid+s]==rv[tid]&&ri[tid+s]<ri[tid]))){
            rv[tid]=rv[tid+s]; ri[tid]=ri[tid+s];
        }
        __syncthreads();
    }
    if(!tid){ mx[row]=rv[0]; am[row]=ri[0]; }
}

__global__ void camx_k(const float* __restrict__ sc,int* __restrict__ am)
{
    int j=blockIdx.x*256+threadIdx.x, b=blockIdx.y;
    const float* base=sc+(long)b*(MM+1)*(MM+1)+j;
    float best=-1e30f; int bi=0;
    for(int i=0;i<MM;i++){ float v=base[(long)i*(MM+1)]; if(v>best){best=v;bi=i;} }
    am[b*MM+j]=bi;
}

__global__ void mt0_k(const float* __restrict__ mx,const int* __restrict__ a0,const int* __restrict__ a1,
                      float* __restrict__ m0,float* __restrict__ ms0,int* __restrict__ v0)
{
    int idx=blockIdx.x*256+threadIdx.x;
    if(idx>=BB*MM) return;
    int b=idx>>11, i=idx&2047, aa=a0[idx];
    bool mut=(a1[b*MM+aa]==i);
    float sc=mut? __expf(mx[idx]) : 0.f;
    bool vv=mut&&(sc>0.1f);
    m0[idx]=vv? (float)aa : -1.f;
    ms0[idx]=sc;
    v0[idx]=vv?1:0;
}

__global__ void mt1_k(const int* __restrict__ a0,const int* __restrict__ a1,const float* __restrict__ ms0,
                      const int* __restrict__ v0,float* __restrict__ m1,float* __restrict__ ms1)
{
    int idx=blockIdx.x*256+threadIdx.x;
    if(idx>=BB*MM) return;
    int b=idx>>11, j=idx&2047, aa=a1[idx];
    bool mut=(a0[b*MM+aa]==j);
    ms1[idx]=mut? ms0[b*MM+aa] : 0.f;
    bool vv=mut&&(v0[b*MM+aa]!=0);
    m1[idx]=vv? (float)aa : -1.f;
}

// ---------------- host-side GEMM wrappers ----------------
struct BD{ long sAb,sAh,sBb,sBh,sCb,sCh; int Hs,nz; };

static void gnn(const float*A,const float*B,const float*bi,const float*rs,float*C,
                int M,int N,int K,int la,int lb,int lc,const BD&d,float os=1.f){
    dim3 g(N/128,M/128,d.nz);
    tgemm_k<128,64,32,false><<<g,256>>>(A,B,bi,rs,C,K,la,lb,lc,d.sAb,d.sAh,d.sBb,d.sBh,d.sCb,d.sCh,d.Hs,os);
}
static void gnt(const float*A,const float*B,const float*bi,const float*rs,float*C,
                int M,int N,int K,int la,int lb,int lc,const BD&d,float os=1.f){
    dim3 g(N/128,M/128,d.nz);
    tgemm_k<128,64,32,true><<<g,256>>>(A,B,bi,rs,C,K,la,lb,lc,d.sAb,d.sAh,d.sBb,d.sBh,d.sCb,d.sCh,d.Hs,os);
}
static void gnn64(const float*A,const float*B,float*C,int la,int lb,int lc,const BD&d){
    dim3 g(1,MM/128,d.nz);
    tgemm_k<64,32,32,false><<<g,256>>>(A,B,(const float*)0,(const float*)0,C,MM,la,lb,lc,d.sAb,d.sAh,d.sBb,d.sBh,d.sCb,d.sCh,d.Hs,1.f);
}

extern "C" void kernel_launch(void* const* d_in, const int* in_sizes, int n_in,
                              void* d_out, int out_size)
{
    const float *kp0=(const float*)d_in[0], *ds0=(const float*)d_in[1];
    const float *kp1=(const float*)d_in[2], *ds1=(const float*)d_in[3];
    const float *isz=(const float*)d_in[4], *Wr=(const float*)d_in[5];
    const float *sqW=(const float*)d_in[6], *sqB=(const float*)d_in[7];
    const float *soW=(const float*)d_in[8], *soB=(const float*)d_in[9];
    const float *sf1=(const float*)d_in[10],*sb1=(const float*)d_in[11];
    const float *sg =(const float*)d_in[12],*sbe=(const float*)d_in[13];
    const float *sf2=(const float*)d_in[14],*sb2=(const float*)d_in[15];
    const float *cqW=(const float*)d_in[16],*cqB=(const float*)d_in[17];
    const float *cvW=(const float*)d_in[18],*cvB=(const float*)d_in[19];
    const float *coW=(const float*)d_in[20],*coB=(const float*)d_in[21];
    const float *cf1=(const float*)d_in[22],*cb1=(const float*)d_in[23];
    const float *cg =(const float*)d_in[24],*cbe=(const float*)d_in[25];
    const float *cf2=(const float*)d_in[26],*cb2=(const float*)d_in[27];
    const float *fpW=(const float*)d_in[28],*fpB=(const float*)d_in[29];
    const float *mw =(const float*)d_in[30],*mb =(const float*)d_in[31];
    float* out=(float*)d_out;

    void* p;
    #define SYM(v,s) cudaGetSymbolAddress(&p,s); float* v=(float*)p;
    SYM(X,g_X) SYM(cb,g_cosb) SYM(sb,g_sinb) SYM(qkv,g_qkv) SYM(attn,g_attn)
    SYM(msg,g_msg) SYM(hb,g_h) SYM(qk,g_qk) SYM(vv,g_v)
    SYM(Sb,g_S) SYM(Pb,g_P) SYM(cm,g_cmax) SYM(cs,g_csum)
    SYM(rK,g_rK) SYM(cK,g_cK) SYM(zb,g_z) SYM(mx0,g_max0)
    #undef SYM
    cudaGetSymbolAddress(&p,g_am0);  int* am0=(int*)p;
    cudaGetSymbolAddress(&p,g_am1);  int* am1=(int*)p;
    cudaGetSymbolAddress(&p,g_vld0); int* vl0=(int*)p;

    cudaMemcpyAsync(X, ds0, (size_t)TOK1*CC*4, cudaMemcpyDeviceToDevice);
    cudaMemcpyAsync(X+(long)TOK1*CC, ds1, (size_t)TOK1*CC*4, cudaMemcpyDeviceToDevice);
    posenc_k<<<TOT*32/256,256>>>(kp0,kp1,Wr,isz,cb,sb);

    const BD one   ={0,0,0,0,0,0,1,1};
    const BD selfS ={2048L*768,64, 2048L*768,64, 4*SEQ2,SEQ2, 4,32};
    const BD selfPV={4*SEQ2,SEQ2, 2048L*768,64, 2048L*256,64, 4,32};
    const BD crosS ={2048L*256,64, 2048L*256,64, 4*SEQ2,SEQ2, 4,16};
    const BD crosPV={4*SEQ2,SEQ2, 2048L*256,64, 2048L*256,64, 4,16};
    const BD epiS  ={2048L*256,0, 2048L*256,0, SEQ2,0, 1,4};

    for(int i=0;i<LL;i++){
        // --- self block (d0 & d1 together) ---
        gnn(X, sqW+(long)i*CC*3*CC, sqB+(long)i*3*CC, 0, qkv, TOT,768,256, 256,768,768, one);
        rope_k<<<TOT,256>>>(qkv,cb,sb);
        gnt(qkv, qkv+256, 0,0, Sb, MM,MM,64, 768,768,MM, selfS, 0.125f);
        rsm_k<<<32*MM,256>>>(Sb,Pb);
        gnn64(Pb, qkv+512, attn, MM,768,256, selfPV);
        gnn(attn, soW+(long)i*CC*CC, soB+(long)i*CC, 0, msg, TOT,256,256, 256,256,256, one);
        // FFN1 split: h = X@W1[:256] + msg@W1[256:] + b1  (no cat buffer)
        gnn(X,   sf1+(long)i*512*512,           sb1+(long)i*512, 0,  hb, TOT,512,256, 256,512,512, one);
        gnn(msg, sf1+(long)i*512*512+256L*512,  0,               hb, hb, TOT,512,256, 256,512,512, one);
        lng_k<<<TOT,256>>>(hb, sg+(long)i*512, sbe+(long)i*512);
        gnn(hb, sf2+(long)i*512*256, sb2+(long)i*256, X, X, TOT,256,512, 512,256,256, one);
        // --- cross block ---
        gnn(X, cqW+(long)i*CC*CC, cqB+(long)i*CC, 0, qk, TOT,256,256, 256,256,256, one);
        gnn(X, cvW+(long)i*CC*CC, cvB+(long)i*CC, 0, vv, TOT,256,256, 256,256,256, one);
        gnt(qk, qk+(long)TOK1*CC, 0,0, Sb, MM,MM,64, 256,256,MM, crosS, 0.125f);
        rsm_k<<<16*MM,256>>>(Sb,Pb);
        cstat_k<<<dim3(8,16),256>>>(Sb,cm,cs);
        tsm_k<<<dim3(64,64,16),dim3(32,8)>>>(Sb,cm,cs,Pb+16*SEQ2);
        gnn64(Pb, vv+(long)TOK1*CC, attn, MM,256,256, crosPV);
        gnn64(Pb+16*SEQ2, vv, attn+(long)TOK1*CC, MM,256,256, crosPV);
        gnn(attn, coW+(long)i*CC*CC, coB+(long)i*CC, 0, msg, TOT,256,256, 256,256,256, one);
        gnn(X,   cf1+(long)i*512*512,           cb1+(long)i*512, 0,  hb, TOT,512,256, 256,512,512, one);
        gnn(msg, cf1+(long)i*512*512+256L*512,  0,               hb, hb, TOT,512,256, 256,512,512, one);
        lng_k<<<TOT,256>>>(hb, cg+(long)i*512, cbe+(long)i*512);
        gnn(hb, cf2+(long)i*512*256, cb2+(long)i*256, X, X, TOT,256,512, 512,256,256, one);
    }

    // --- matching epilogue ---
    gnn(X, fpW, fpB, 0, qk, TOT,256,256, 256,256,256, one, 0.25f);
    gnt(qk, qk+(long)TOK1*CC, 0,0, Sb, MM,MM,256, 256,256,MM, epiS);
    gemv_k<<<TOT/8,256>>>(X,mw,mb,zb,TOT);
    rlse_k<<<BB*MM,256>>>(Sb,rK);
    clse_k<<<dim3(8,BB),256>>>(Sb,cK);
    float* scores=out+4L*BB*MM;
    fill_k<<<dim3((MM+256)/256,BB*(MM+1)),256>>>(Sb,rK,cK,zb,zb+TOK1,scores);
    ramx_k<<<BB*MM,256>>>(scores,mx0,am0);
    camx_k<<<dim3(8,BB),256>>>(scores,am1);
    mt0_k<<<BB*MM/256,256>>>(mx0,am0,am1,out,out+2L*BB*MM,vl0);
    mt1_k<<<BB*MM/256,256>>>(am0,am1,out+2L*BB*MM,vl0,out+(long)BB*MM,out+3L*BB*MM);
}

// round 13
// speedup vs baseline: 1.6222x; 1.0852x over previous
#include <cuda_runtime.h>
#include <math.h>

#define BB 4
#define MM 2048
#define CC 256
#define HH 4
#define HD 64
#define LL 9
#define TOK1 (BB*MM)          // 8192
#define TOT  (2*TOK1)         // 16384
#define SEQ2 ((long)MM*MM)

// scratch (static device arrays; no allocations allowed)
__device__ float g_X[TOT*CC];
__device__ float g_cosb[TOT*HD];
__device__ float g_sinb[TOT*HD];
__device__ float g_qkv[TOT*3*CC];
__device__ float g_attn[TOT*CC];
__device__ float g_msg[TOT*CC];
__device__ float g_h[TOT*2*CC];
__device__ float g_qk[TOT*CC];
__device__ float g_v[TOT*CC];
__device__ float g_S[32*SEQ2];
__device__ float g_P[32*SEQ2];
__device__ float g_rK[BB*MM];
__device__ float g_cK[BB*MM];
__device__ float g_z[TOT];
__device__ float g_max0[BB*MM];
__device__ int   g_am0[BB*MM];
__device__ int   g_am1[BB*MM];
__device__ int   g_vld0[BB*MM];

// ---------------- common tensor-core helpers ----------------
__device__ __forceinline__ void mma8(float* c, const unsigned* a, const unsigned* b){
    asm volatile(
      "mma.sync.aligned.m16n8k8.row.col.f32.tf32.tf32.f32 "
      "{%0,%1,%2,%3},{%4,%5,%6,%7},{%8,%9},{%0,%1,%2,%3};"
      : "+f"(c[0]),"+f"(c[1]),"+f"(c[2]),"+f"(c[3])
      : "r"(a[0]),"r"(a[1]),"r"(a[2]),"r"(a[3]),"r"(b[0]),"r"(b[1]));
}
// hi = top-19-bit truncation (what HMMA.TF32 consumes); lo = exact residual.
__device__ __forceinline__ void hspl(float v, unsigned& hi, unsigned& lo){
    unsigned u=__float_as_uint(v)&0xFFFFE000u;
    hi=u;
    lo=__float_as_uint(__fsub_rn(v,__uint_as_float(u)));
}
__device__ __forceinline__ unsigned sptr(const void* p){
    return (unsigned)__cvta_generic_to_shared(p);
}
__device__ __forceinline__ void cpa16(unsigned dst, const void* src){
    asm volatile("cp.async.cg.shared.global [%0],[%1],16;"::"r"(dst),"l"(src));
}
__device__ __forceinline__ void cpc(){ asm volatile("cp.async.commit_group;"); }
__device__ __forceinline__ void cpw0(){ asm volatile("cp.async.wait_group 0;"); }

// ---------------- 3xTF32 GEMM, cp.async double-buffered (proven) ----------
// C[M,N] = os*(A@B(^T) + bias) + resid ; batched with (batch,head) strides.
template<int BN,int WM,int WN,bool TB>
__global__ void __launch_bounds__(256)
tgemm_k(const float* __restrict__ A, const float* __restrict__ Bm,
        const float* __restrict__ bias, const float* __restrict__ resid,
        float* __restrict__ C, int Kd, int lda,int ldb,int ldc,
        long sAb,long sAh,long sBb,long sBh,long sCb,long sCh,int Hs,float os)
{
    constexpr int BM=128;
    constexpr int MT=WM/16, NT2=WN/8;
    constexpr int NWC=BN/WN;
    constexpr int NB=BN/64;
    constexpr int BR  = TB ? BN : 16;
    constexpr int BCL = TB ? 20 : BN+8;
    __shared__ __align__(16) float As[2][BM][20];
    __shared__ __align__(16) float Bs[2][BR][BCL];

    const int z=blockIdx.z, zb=z/Hs, zh=z-zb*Hs;
    A +=(long)zb*sAb+(long)zh*sAh;
    Bm+=(long)zb*sBb+(long)zh*sBh;
    C +=(long)zb*sCb+(long)zh*sCh;
    const float* Rp = resid? resid+(long)zb*sCb+(long)zh*sCh : (const float*)0;

    const int tid=threadIdx.x;
    const int warp=tid>>5, lane=tid&31, gid=lane>>2, tig=lane&3;
    const int wR=warp/NWC, wC=warp%NWC;
    const int bm0=blockIdx.y*BM, bn0=blockIdx.x*BN;
    const int arow=tid>>2, akc=tid&3;

    float cr[MT][NT2][4];
    #pragma unroll
    for(int i=0;i<MT;i++)
        #pragma unroll
        for(int j=0;j<NT2;j++)
            #pragma unroll
            for(int q=0;q<4;q++) cr[i][j][q]=0.f;

    auto loadA=[&](int st,int k0){
        #pragma unroll
        for(int i=0;i<2;i++){
            int row=arow+i*64;
            cpa16(sptr(&As[st][row][akc*4]), A+(long)(bm0+row)*lda+k0+akc*4);
        }
    };
    auto loadB=[&](int st,int k0){
        if(!TB){
            #pragma unroll
            for(int i=0;i<NB;i++){
                int k = (BN==128)? (tid>>5)+i*8 : (tid>>4);
                int nc= (BN==128)? (tid&31)    : (tid&15);
                cpa16(sptr(&Bs[st][k][nc*4]), Bm+(long)(k0+k)*ldb+bn0+nc*4);
            }
        } else {
            #pragma unroll
            for(int i=0;i<NB;i++){
                int n=arow+i*64;
                cpa16(sptr(&Bs[st][n][akc*4]), Bm+(long)(bn0+n)*ldb+k0+akc*4);
            }
        }
    };

    const int nk=Kd/16;
    loadA(0,0); loadB(0,0); cpc();

    for(int it=0; it<nk; it++){
        cpw0(); __syncthreads();
        if(it+1<nk){ loadA((it+1)&1,(it+1)*16); loadB((it+1)&1,(it+1)*16); cpc(); }
        const int st=it&1;

        #pragma unroll
        for(int ks=0;ks<2;ks++){
            const int k=ks*8+tig;
            unsigned ah[MT][4], al[MT][4];
            #pragma unroll
            for(int mi=0;mi<MT;mi++){
                int r=wR*WM+mi*16+gid;
                hspl(As[st][r][k],     ah[mi][0], al[mi][0]);
                hspl(As[st][r+8][k],   ah[mi][1], al[mi][1]);
                hspl(As[st][r][k+4],   ah[mi][2], al[mi][2]);
                hspl(As[st][r+8][k+4], ah[mi][3], al[mi][3]);
            }
            unsigned bh[NT2][2], bl[NT2][2];
            #pragma unroll
            for(int ni=0;ni<NT2;ni++){
                int cn=wC*WN+ni*8+gid;
                if(TB){
                    hspl(Bs[st][cn][k],   bh[ni][0], bl[ni][0]);
                    hspl(Bs[st][cn][k+4], bh[ni][1], bl[ni][1]);
                } else {
                    hspl(Bs[st][k][cn],   bh[ni][0], bl[ni][0]);
                    hspl(Bs[st][k+4][cn], bh[ni][1], bl[ni][1]);
                }
            }
            #pragma unroll
            for(int mi=0;mi<MT;mi++)
                #pragma unroll
                for(int ni=0;ni<NT2;ni++){
                    mma8(cr[mi][ni],ah[mi],bl[ni]);
                    mma8(cr[mi][ni],al[mi],bh[ni]);
                    mma8(cr[mi][ni],ah[mi],bh[ni]);
                }
        }
    }

    #pragma unroll
    for(int mi=0;mi<MT;mi++){
        #pragma unroll
        for(int ni=0;ni<NT2;ni++){
            long r0=bm0+wR*WM+mi*16+gid;
            int  cn=bn0+wC*WN+ni*8+2*tig;
            float b0=bias?bias[cn]:0.f, b1=bias?bias[cn+1]:0.f;
            float v0=(cr[mi][ni][0]+b0)*os, v1=(cr[mi][ni][1]+b1)*os;
            float v2=(cr[mi][ni][2]+b0)*os, v3=(cr[mi][ni][3]+b1)*os;
            if(Rp){
                v0+=Rp[r0*ldc+cn];     v1+=Rp[r0*ldc+cn+1];
                v2+=Rp[(r0+8)*ldc+cn]; v3+=Rp[(r0+8)*ldc+cn+1];
            }
            *reinterpret_cast<float2*>(&C[r0*ldc+cn])    =make_float2(v0,v1);
            *reinterpret_cast<float2*>(&C[(r0+8)*ldc+cn])=make_float2(v2,v3);
        }
    }
}

// ---------------- elementwise / reduction kernels ----------------
__global__ void posenc_k(const float* __restrict__ k0,const float* __restrict__ k1,
                         const float* __restrict__ Wr,const float* __restrict__ isz,
                         float* __restrict__ cb,float* __restrict__ sb)
{
    int idx=blockIdx.x*256+threadIdx.x;
    if(idx>=TOT*32) return;
    int t=idx>>5, p=idx&31;
    const float* kp=(t<TOK1)? k0+(long)t*2 : k1+(long)(t-TOK1)*2;
    float w=isz[0],h=isz[1],sc=0.5f*fmaxf(w,h);
    float nx=(kp[0]-0.5f*w)/sc, ny=(kp[1]-0.5f*h)/sc;
    float pr=nx*Wr[p]+ny*Wr[32+p];
    float c=cosf(pr), s=sinf(pr);
    cb[t*HD+2*p]=c; cb[t*HD+2*p+1]=c;
    sb[t*HD+2*p]=s; sb[t*HD+2*p+1]=s;
}

__global__ void rope_k(float* __restrict__ qkv,const float* __restrict__ cb,const float* __restrict__ sb)
{
    int idx=blockIdx.x*256+threadIdx.x;
    if(idx>=TOT*256) return;
    int t=idx>>8, p=idx&255, c0=p*2, d=c0&63;
    float c=cb[t*HD+d], s=sb[t*HD+d];
    float* q=qkv+(long)t*768+c0;
    float a=q[0], b=q[1];
    q[0]=a*c-b*s; q[1]=b*c+a*s;
}

__global__ void rsm_k(const float* __restrict__ S,float* __restrict__ P)
{
    long row=blockIdx.x;
    const float* x=S+row*(long)MM; float* y=P+row*(long)MM;
    int tid=threadIdx.x;
    float v[8], m=-1e30f;
    #pragma unroll
    for(int r=0;r<8;r++){ v[r]=x[tid+r*256]; m=fmaxf(m,v[r]); }
    __shared__ float red[256];
    red[tid]=m; __syncthreads();
    for(int s=128;s>0;s>>=1){ if(tid<s) red[tid]=fmaxf(red[tid],red[tid+s]); __syncthreads(); }
    m=red[0]; __syncthreads();
    float sum=0.f;
    #pragma unroll
    for(int r=0;r<8;r++){ v[r]=__expf(v[r]-m); sum+=v[r]; }
    red[tid]=sum; __syncthreads();
    for(int s=128;s>0;s>>=1){ if(tid<s) red[tid]+=red[tid+s]; __syncthreads(); }
    float inv=1.f/red[0];
    #pragma unroll
    for(int r=0;r<8;r++) y[tid+r*256]=v[r]*inv;
}

__device__ __forceinline__ float gelu_t(float y){
    return 0.5f*y*(1.f+tanhf(0.7978845608028654f*(y+0.044715f*y*y*y)));
}

__global__ void lng_k(float* __restrict__ h,const float* __restrict__ g,const float* __restrict__ bt)
{
    long row=blockIdx.x; float* x=h+row*512;
    int tid=threadIdx.x;
    float a=x[tid], b=x[tid+256];
    __shared__ float s1[256],s2[256];
    s1[tid]=a+b; s2[tid]=a*a+b*b; __syncthreads();
    for(int s=128;s>0;s>>=1){ if(tid<s){ s1[tid]+=s1[tid+s]; s2[tid]+=s2[tid+s]; } __syncthreads(); }
    float mu=s1[0]*(1.f/512.f), var=s2[0]*(1.f/512.f)-mu*mu, rs=rsqrtf(var+1e-5f);
    x[tid]    =gelu_t((a-mu)*rs*g[tid]    +bt[tid]);
    x[tid+256]=gelu_t((b-mu)*rs*g[tid+256]+bt[tid+256]);
}

__global__ void gemv_k(const float* __restrict__ X,const float* __restrict__ w,
                       const float* __restrict__ b,float* __restrict__ z,int rows)
{
    int gw=(blockIdx.x*blockDim.x+threadIdx.x)>>5, lane=threadIdx.x&31;
    if(gw>=rows) return;
    const float* xr=X+(long)gw*CC;
    float s=0.f;
    for(int c=lane;c<CC;c+=32) s+=xr[c]*w[c];
    for(int o=16;o;o>>=1) s+=__shfl_down_sync(0xffffffffu,s,o);
    if(!lane) z[gw]=s+b[0];
}

__global__ void rlse_k(const float* __restrict__ sim,float* __restrict__ rK)
{
    long row=blockIdx.x;
    const float* x=sim+row*(long)MM;
    int tid=threadIdx.x;
    float v[8], m=-1e30f;
    #pragma unroll
    for(int r=0;r<8;r++){ v[r]=x[tid+r*256]; m=fmaxf(m,v[r]); }
    __shared__ float red[256];
    red[tid]=m; __syncthreads();
    for(int s=128;s>0;s>>=1){ if(tid<s) red[tid]=fmaxf(red[tid],red[tid+s]); __syncthreads(); }
    m=red[0]; __syncthreads();
    float sum=0.f;
    #pragma unroll
    for(int r=0;r<8;r++) sum+=__expf(v[r]-m);
    red[tid]=sum; __syncthreads();
    for(int s=128;s>0;s>>=1){ if(tid<s) red[tid]+=red[tid+s]; __syncthreads(); }
    if(!tid) rK[row]=m+logf(red[0]);
}

__device__ __forceinline__ float logsigf(float x){
    return (x>=0.f)? -log1pf(__expf(-x)) : x-log1pf(__expf(x));
}

__global__ void fill_k(const float* __restrict__ sim,const float* __restrict__ rK,
                       const float* __restrict__ cK,const float* __restrict__ z0,
                       const float* __restrict__ z1,float* __restrict__ out)
{
    int j=blockIdx.x*256+threadIdx.x;
    if(j>MM) return;
    int bi=blockIdx.y, b=bi/(MM+1), i=bi-b*(MM+1);
    float v;
    if(i<MM&&j<MM)
        v=2.f*sim[(long)b*SEQ2+(long)i*MM+j]-rK[b*MM+i]-cK[b*MM+j]
          +logsigf(z0[b*MM+i])+logsigf(z1[b*MM+j]);
    else if(i<MM) v=logsigf(-z0[b*MM+i]);
    else if(j<MM) v=logsigf(-z1[b*MM+j]);
    else v=0.f;
    out[((long)b*(MM+1)+i)*(MM+1)+j]=v;
}

__global__ void ramx_k(const float* __restrict__ sc,float* __restrict__ mx,int* __restrict__ am)
{
    long row=blockIdx.x;
    int b=(int)(row>>11), i=(int)(row&2047);
    const float* x=sc+((long)b*(MM+1)+i)*(MM+1);
    int tid=threadIdx.x;
    float best=-1e30f; int bi=0;
    for(int j=tid;j<MM;j+=256){ float v=x[j]; if(v>best){best=v;bi=j;} }
    __shared__ float rv[256]; __shared__ int ri[256];
    rv[tid]=best; ri[tid]=bi; __syncthreads();
    for(int s=128;s>0;s>>=1){
        if(tid<s && (rv[tid+s]>rv[tid]||(rv[tid+s]==rv[tid]&&ri[tid+s]<ri[tid]))){
            rv[tid]=rv[tid+s]; ri[tid]=ri[tid+s];
        }
        __syncthreads();
    }
    if(!tid){ mx[row]=rv[0]; am[row]=ri[0]; }
}

__global__ void camx_k(const float* __restrict__ sc,int* __restrict__ am)
{
    int j=blockIdx.x*256+threadIdx.x, b=blockIdx.y;
    const float* base=sc+(long)b*(MM+1)*(MM+1)+j;
    float best=-1e30f; int bi=0;
    for(int i=0;i<MM;i++){ float v=base[(long)i*(MM+1)]; if(v>best){best=v;bi=i;} }
    am[b*MM+j]=bi;
}

__global__ void mt0_k(const float* __restrict__ mx,const int* __restrict__ a0,const int* __restrict__ a1,
                      float* __restrict__ m0,float* __restrict__ ms0,int* __restrict__ v0)
{
    int idx=blockIdx.x*256+threadIdx.x;
    if(idx>=BB*MM) return;
    int b=idx>>11, i=idx&2047, aa=a0[idx];
    bool mut=(a1[b*MM+aa]==i);
    float sc=mut? __expf(mx[idx]) : 0.f;
    bool vv=mut&&(sc>0.1f);
    m0[idx]=vv? (float)aa : -1.f;
    ms0[idx]=sc;
    v0[idx]=vv?1:0;
}

__global__ void mt1_k(const int* __restrict__ a0,const int* __restrict__ a1,const float* __restrict__ ms0,
                      const int* __restrict__ v0,float* __restrict__ m1,float* __restrict__ ms1)
{
    int idx=blockIdx.x*256+threadIdx.x;
    if(idx>=BB*MM) return;
    int b=idx>>11, j=idx&2047, aa=a1[idx];
    bool mut=(a0[b*MM+aa]==j);
    ms1[idx]=mut? ms0[b*MM+aa] : 0.f;
    bool vv=mut&&(v0[b*MM+aa]!=0);
    m1[idx]=vv? (float)aa : -1.f;
}

// ---------------- host-side GEMM wrappers ----------------
struct BD{ long sAb,sAh,sBb,sBh,sCb,sCh; int Hs,nz; };

static void gnn(const float*A,const float*B,const float*bi,const float*rs,float*C,
                int M,int N,int K,int la,int lb,int lc,const BD&d,float os=1.f){
    dim3 g(N/128,M/128,d.nz);
    tgemm_k<128,64,32,false><<<g,256>>>(A,B,bi,rs,C,K,la,lb,lc,d.sAb,d.sAh,d.sBb,d.sBh,d.sCb,d.sCh,d.Hs,os);
}
static void gnt(const float*A,const float*B,const float*bi,const float*rs,float*C,
                int M,int N,int K,int la,int lb,int lc,const BD&d,float os=1.f){
    dim3 g(N/128,M/128,d.nz);
    tgemm_k<128,64,32,true><<<g,256>>>(A,B,bi,rs,C,K,la,lb,lc,d.sAb,d.sAh,d.sBb,d.sBh,d.sCb,d.sCh,d.Hs,os);
}
static void gnn64(const float*A,const float*B,float*C,int la,int lb,int lc,const BD&d){
    dim3 g(1,MM/128,d.nz);
    tgemm_k<64,32,32,false><<<g,256>>>(A,B,(const float*)0,(const float*)0,C,MM,la,lb,lc,d.sAb,d.sAh,d.sBb,d.sBh,d.sCb,d.sCh,d.Hs,1.f);
}

extern "C" void kernel_launch(void* const* d_in, const int* in_sizes, int n_in,
                              void* d_out, int out_size)
{
    const float *kp0=(const float*)d_in[0], *ds0=(const float*)d_in[1];
    const float *kp1=(const float*)d_in[2], *ds1=(const float*)d_in[3];
    const float *isz=(const float*)d_in[4], *Wr=(const float*)d_in[5];
    const float *sqW=(const float*)d_in[6], *sqB=(const float*)d_in[7];
    const float *soW=(const float*)d_in[8], *soB=(const float*)d_in[9];
    const float *sf1=(const float*)d_in[10],*sb1=(const float*)d_in[11];
    const float *sg =(const float*)d_in[12],*sbe=(const float*)d_in[13];
    const float *sf2=(const float*)d_in[14],*sb2=(const float*)d_in[15];
    const float *cqW=(const float*)d_in[16],*cqB=(const float*)d_in[17];
    const float *cvW=(const float*)d_in[18],*cvB=(const float*)d_in[19];
    const float *coW=(const float*)d_in[20],*coB=(const float*)d_in[21];
    const float *cf1=(const float*)d_in[22],*cb1=(const float*)d_in[23];
    const float *cg =(const float*)d_in[24],*cbe=(const float*)d_in[25];
    const float *cf2=(const float*)d_in[26],*cb2=(const float*)d_in[27];
    const float *fpW=(const float*)d_in[28],*fpB=(const float*)d_in[29];
    const float *mw =(const float*)d_in[30],*mb =(const float*)d_in[31];
    float* out=(float*)d_out;

    void* p;
    #define SYM(v,s) cudaGetSymbolAddress(&p,s); float* v=(float*)p;
    SYM(X,g_X) SYM(cb,g_cosb) SYM(sb,g_sinb) SYM(qkv,g_qkv) SYM(attn,g_attn)
    SYM(msg,g_msg) SYM(hb,g_h) SYM(qk,g_qk) SYM(vv,g_v)
    SYM(Sb,g_S) SYM(Pb,g_P)
    SYM(rK,g_rK) SYM(cK,g_cK) SYM(zb,g_z) SYM(mx0,g_max0)
    #undef SYM
    cudaGetSymbolAddress(&p,g_am0);  int* am0=(int*)p;
    cudaGetSymbolAddress(&p,g_am1);  int* am1=(int*)p;
    cudaGetSymbolAddress(&p,g_vld0); int* vl0=(int*)p;

    cudaMemcpyAsync(X, ds0, (size_t)TOK1*CC*4, cudaMemcpyDeviceToDevice);
    cudaMemcpyAsync(X+(long)TOK1*CC, ds1, (size_t)TOK1*CC*4, cudaMemcpyDeviceToDevice);
    posenc_k<<<TOT*32/256,256>>>(kp0,kp1,Wr,isz,cb,sb);

    const BD one   ={0,0,0,0,0,0,1,1};
    const BD selfS ={2048L*768,64, 2048L*768,64, 4*SEQ2,SEQ2, 4,32};
    const BD selfPV={4*SEQ2,SEQ2, 2048L*768,64, 2048L*256,64, 4,32};
    const BD crosS ={2048L*256,64, 2048L*256,64, 4*SEQ2,SEQ2, 4,16};
    const BD crosPV={4*SEQ2,SEQ2, 2048L*256,64, 2048L*256,64, 4,16};
    const BD epiS  ={2048L*256,0, 2048L*256,0, SEQ2,0, 1,4};

    for(int i=0;i<LL;i++){
        // --- self block (d0 & d1 together) ---
        gnn(X, sqW+(long)i*CC*3*CC, sqB+(long)i*3*CC, 0, qkv, TOT,768,256, 256,768,768, one);
        rope_k<<<TOT,256>>>(qkv,cb,sb);
        gnt(qkv, qkv+256, 0,0, Sb, MM,MM,64, 768,768,MM, selfS, 0.125f);
        rsm_k<<<32*MM,256>>>(Sb,Pb);
        gnn64(Pb, qkv+512, attn, MM,768,256, selfPV);
        gnn(attn, soW+(long)i*CC*CC, soB+(long)i*CC, 0, msg, TOT,256,256, 256,256,256, one);
        // FFN1 split: h = X@W1[:256] + msg@W1[256:] + b1
        gnn(X,   sf1+(long)i*512*512,           sb1+(long)i*512, 0,  hb, TOT,512,256, 256,512,512, one);
        gnn(msg, sf1+(long)i*512*512+256L*512,  0,               hb, hb, TOT,512,256, 256,512,512, one);
        lng_k<<<TOT,256>>>(hb, sg+(long)i*512, sbe+(long)i*512);
        gnn(hb, sf2+(long)i*512*256, sb2+(long)i*256, X, X, TOT,256,512, 512,256,256, one);
        // --- cross block: S and S^T both via GEMM, one wide row-softmax ---
        gnn(X, cqW+(long)i*CC*CC, cqB+(long)i*CC, 0, qk, TOT,256,256, 256,256,256, one);
        gnn(X, cvW+(long)i*CC*CC, cvB+(long)i*CC, 0, vv, TOT,256,256, 256,256,256, one);
        gnt(qk,               qk+(long)TOK1*CC, 0,0, Sb,           MM,MM,64, 256,256,MM, crosS, 0.125f);
        gnt(qk+(long)TOK1*CC, qk,               0,0, Sb+16*SEQ2,   MM,MM,64, 256,256,MM, crosS, 0.125f);
        rsm_k<<<32*MM,256>>>(Sb,Pb);    // rows 0..16*2048-1: P ; rows 16*2048..: P^T
        gnn64(Pb,          vv+(long)TOK1*CC, attn,               MM,256,256, crosPV);
        gnn64(Pb+16*SEQ2,  vv,               attn+(long)TOK1*CC, MM,256,256, crosPV);
        gnn(attn, coW+(long)i*CC*CC, coB+(long)i*CC, 0, msg, TOT,256,256, 256,256,256, one);
        gnn(X,   cf1+(long)i*512*512,           cb1+(long)i*512, 0,  hb, TOT,512,256, 256,512,512, one);
        gnn(msg, cf1+(long)i*512*512+256L*512,  0,               hb, hb, TOT,512,256, 256,512,512, one);
        lng_k<<<TOT,256>>>(hb, cg+(long)i*512, cbe+(long)i*512);
        gnn(hb, cf2+(long)i*512*256, cb2+(long)i*256, X, X, TOT,256,512, 512,256,256, one);
    }

    // --- matching epilogue ---
    gnn(X, fpW, fpB, 0, qk, TOT,256,256, 256,256,256, one, 0.25f);
    gnt(qk, qk+(long)TOK1*CC, 0,0, Sb, MM,MM,256, 256,256,MM, epiS);
    gnt(qk+(long)TOK1*CC, qk, 0,0, Pb, MM,MM,256, 256,256,MM, epiS);   // sim^T
    gemv_k<<<TOT/8,256>>>(X,mw,mb,zb,TOT);
    rlse_k<<<BB*MM,256>>>(Sb,rK);
    rlse_k<<<BB*MM,256>>>(Pb,cK);   // row-LSE of sim^T = column-LSE of sim
    float* scores=out+4L*BB*MM;
    fill_k<<<dim3((MM+256)/256,BB*(MM+1)),256>>>(Sb,rK,cK,zb,zb+TOK1,scores);
    ramx_k<<<BB*MM,256>>>(scores,mx0,am0);
    camx_k<<<dim3(8,BB),256>>>(scores,am1);
    mt0_k<<<BB*MM/256,256>>>(mx0,am0,am1,out,out+2L*BB*MM,vl0);
    mt1_k<<<BB*MM/256,256>>>(am0,am1,out+2L*BB*MM,vl0,out+(long)BB*MM,out+3L*BB*MM);
}